// round 16
// baseline (speedup 1.0000x reference)
#include <cuda_runtime.h>
#include <math.h>
#include <stdint.h>

#define NMAX 50000
#define CAP  128
#define KSPLIT 4

__device__ float g_bufA[NMAX * 32];
__device__ float g_bufB[NMAX * 32];
__device__ int2  g_csr[(size_t)NMAX * CAP];
__device__ int   g_cnt[NMAX];

__device__ __forceinline__ float selu_f(float x) {
    const float alpha = 1.6732632423543772f;
    const float scale = 1.0507009873554805f;
    return x > 0.f ? scale * x : scale * alpha * (expf(x) - 1.f);
}

typedef unsigned long long ull;
__device__ __forceinline__ ull pack2(float a) {
    ull r; asm("mov.b64 %0, {%1, %1};" : "=l"(r) : "f"(a)); return r;
}
__device__ __forceinline__ void fma2(ull& d, ull a, ull b) {
    asm("fma.rn.f32x2 %0, %1, %2, %3;" : "=l"(d) : "l"(a), "l"(b), "l"(d));
}

// ---------------------------------------------------------------------------
// CSR build: 2 edges per thread, vectorized meta loads.
// ---------------------------------------------------------------------------
__global__ void __launch_bounds__(256) build_csr_kernel(const int* __restrict__ rows,
                                                        const int* __restrict__ cols,
                                                        const float* __restrict__ vals,
                                                        int E) {
    int e = (blockIdx.x * 256 + threadIdx.x) * 2;
    if (e + 1 < E) {
        int2   rr = *(const int2*)(rows + e);
        int2   cc = *(const int2*)(cols + e);
        float2 vv = *(const float2*)(vals + e);
        int p0 = atomicAdd(&g_cnt[rr.x], 1);
        if (p0 < CAP)
            g_csr[(size_t)rr.x * CAP + p0] = make_int2(cc.x, __float_as_int(vv.x));
        int p1 = atomicAdd(&g_cnt[rr.y], 1);
        if (p1 < CAP)
            g_csr[(size_t)rr.y * CAP + p1] = make_int2(cc.y, __float_as_int(vv.y));
    } else if (e < E) {
        int r = rows[e];
        int p = atomicAdd(&g_cnt[r], 1);
        if (p < CAP)
            g_csr[(size_t)r * CAP + p] = make_int2(cols[e], __float_as_int(vals[e]));
    }
}

// ---------------------------------------------------------------------------
// GEMM1 (R13 measured-best, FROZEN): split-K x4, col-pair FFMA2 inner loop,
// RED.128 accumulate into zeroed sup.
// ---------------------------------------------------------------------------
__global__ void __launch_bounds__(128) gemm1_kernel(const float* __restrict__ x,
                                                    const float* __restrict__ w,
                                                    float* __restrict__ sup, int N) {
    __shared__ float xs[128][33];
    __shared__ float ws[32][32];

    int tid  = threadIdx.x;
    int rb   = blockIdx.x >> 2;
    int ks   = blockIdx.x & 3;
    int row0 = rb * 128;
    int kbeg = ks * 256;
    int trow = (tid >> 2) * 4;
    int tcol = (tid & 3) * 8;

    ull acc[4][4];
#pragma unroll
    for (int i = 0; i < 4; i++)
#pragma unroll
        for (int j = 0; j < 4; j++) acc[i][j] = 0ull;

    for (int kc = 0; kc < 8; kc++) {
        int k0 = kbeg + kc * 32;
#pragma unroll
        for (int i = 0; i < 2; i++) {
            int idx = i * 128 + tid;
            ((float4*)ws)[idx] = ((const float4*)(w + (size_t)k0 * 32))[idx];
        }
#pragma unroll
        for (int i = 0; i < 8; i++) {
            int idx = i * 128 + tid;
            int r   = idx >> 3;
            int kk  = (idx & 7) * 4;
            float4 v = make_float4(0.f, 0.f, 0.f, 0.f);
            if (row0 + r < N)
                v = *(const float4*)(x + (size_t)(row0 + r) * 1024 + k0 + kk);
            xs[r][kk] = v.x; xs[r][kk + 1] = v.y; xs[r][kk + 2] = v.z; xs[r][kk + 3] = v.w;
        }
        __syncthreads();

#pragma unroll
        for (int k = 0; k < 32; k++) {
            ull B[4];
#pragma unroll
            for (int j = 0; j < 4; j++) B[j] = *(const ull*)&ws[k][tcol + 2 * j];
#pragma unroll
            for (int i = 0; i < 4; i++) {
                ull A = pack2(xs[trow + i][k]);
                fma2(acc[i][0], A, B[0]);
                fma2(acc[i][1], A, B[1]);
                fma2(acc[i][2], A, B[2]);
                fma2(acc[i][3], A, B[3]);
            }
        }
        __syncthreads();
    }

#pragma unroll
    for (int i = 0; i < 4; i++) {
        int r = row0 + trow + i;
        if (r < N) {
            union { ull u; float2 f; } u0, u1, u2, u3;
            u0.u = acc[i][0]; u1.u = acc[i][1]; u2.u = acc[i][2]; u3.u = acc[i][3];
            float* dst = sup + (size_t)r * 32 + tcol;
            asm volatile("red.global.add.v4.f32 [%0], {%1,%2,%3,%4};"
                         :: "l"(dst), "f"(u0.f.x), "f"(u0.f.y), "f"(u1.f.x), "f"(u1.f.y)
                         : "memory");
            asm volatile("red.global.add.v4.f32 [%0], {%1,%2,%3,%4};"
                         :: "l"(dst + 4), "f"(u2.f.x), "f"(u2.f.y), "f"(u3.f.x), "f"(u3.f.y)
                         : "memory");
        }
    }
}

// ---------------------------------------------------------------------------
// SpMM core v5 (R12 measured-good, FROZEN): 4 lane-groups x float4.
// ---------------------------------------------------------------------------
__device__ __forceinline__ float spmm_row_v5(const float* __restrict__ sup,
                                             int row, int lane) {
    int deg = g_cnt[row];
    if (deg > CAP) deg = CAP;
    const int2* base = g_csr + (size_t)row * CAP;
    int g   = lane >> 3;
    int sub = lane & 7;

    float4 acc = make_float4(0.f, 0.f, 0.f, 0.f);

    for (int c0 = 0; c0 < deg; c0 += 32) {
        int rem = deg - c0;
        if (rem > 32) rem = 32;
        int2 ev = make_int2(0, 0);
        if (lane < rem) ev = base[c0 + lane];

        if (rem == 32) {
#pragma unroll
            for (int half = 0; half < 2; half++) {
                float4 sv[4]; float vv[4];
#pragma unroll
                for (int s = 0; s < 4; s++) {
                    int src = (half * 4 + s) * 4 + g;
                    int col = __shfl_sync(0xffffffffu, ev.x, src);
                    vv[s] = __int_as_float(__shfl_sync(0xffffffffu, ev.y, src));
                    sv[s] = __ldg((const float4*)(sup + (size_t)col * 32) + sub);
                }
#pragma unroll
                for (int s = 0; s < 4; s++) {
                    acc.x = fmaf(vv[s], sv[s].x, acc.x);
                    acc.y = fmaf(vv[s], sv[s].y, acc.y);
                    acc.z = fmaf(vv[s], sv[s].z, acc.z);
                    acc.w = fmaf(vv[s], sv[s].w, acc.w);
                }
            }
        } else {
            int nst = (rem + 3) >> 2;
            for (int s = 0; s < nst; s++) {
                int src = s * 4 + g;
                int col = __shfl_sync(0xffffffffu, ev.x, src);
                float v = __int_as_float(__shfl_sync(0xffffffffu, ev.y, src));
                float4 sv = __ldg((const float4*)(sup + (size_t)col * 32) + sub);
                acc.x = fmaf(v, sv.x, acc.x);
                acc.y = fmaf(v, sv.y, acc.y);
                acc.z = fmaf(v, sv.z, acc.z);
                acc.w = fmaf(v, sv.w, acc.w);
            }
        }
    }

#pragma unroll
    for (int off = 8; off <= 16; off <<= 1) {
        acc.x += __shfl_xor_sync(0xffffffffu, acc.x, off);
        acc.y += __shfl_xor_sync(0xffffffffu, acc.y, off);
        acc.z += __shfl_xor_sync(0xffffffffu, acc.z, off);
        acc.w += __shfl_xor_sync(0xffffffffu, acc.w, off);
    }

    int src = lane >> 2;
    float c0 = __shfl_sync(0xffffffffu, acc.x, src);
    float c1 = __shfl_sync(0xffffffffu, acc.y, src);
    float c2 = __shfl_sync(0xffffffffu, acc.z, src);
    float c3 = __shfl_sync(0xffffffffu, acc.w, src);
    int comp = lane & 3;
    return comp == 0 ? c0 : comp == 1 ? c1 : comp == 2 ? c2 : c3;
}

// ---------------------------------------------------------------------------
// Fused: agg = SpMM(sup_in); h = selu(agg)+b; sup_out = h @ w
// ---------------------------------------------------------------------------
__global__ void __launch_bounds__(256) spmm_selu_gemm_kernel(const float* __restrict__ sup_in,
                                                             const float* __restrict__ bias,
                                                             const float* __restrict__ w,
                                                             float* __restrict__ sup_out,
                                                             int N) {
    __shared__ float ws[1024];
    __shared__ float bs[32];
    int tid = threadIdx.x;
    for (int i = tid; i < 1024; i += 256) ws[i] = w[i];
    if (tid < 32) bs[tid] = bias[tid];
    __syncthreads();

    int warp = tid >> 5;
    int lane = tid & 31;
    int row  = blockIdx.x * 8 + warp;
    if (row >= N) return;

    float acc = spmm_row_v5(sup_in, row, lane);
    float h = selu_f(acc) + bs[lane];

    float o = 0.f;
#pragma unroll
    for (int k = 0; k < 32; k++) {
        float hk = __shfl_sync(0xffffffffu, h, k);
        o = fmaf(hk, ws[k * 32 + lane], o);
    }
    sup_out[(size_t)row * 32 + lane] = o;
}

// ---------------------------------------------------------------------------
// Fused final: agg = SpMM; h = selu+b3; classifier heads → out
// ---------------------------------------------------------------------------
__global__ void __launch_bounds__(256) spmm_final_kernel(const float* __restrict__ sup_in,
                                                         const float* __restrict__ bias,
                                                         const float* __restrict__ cw0,
                                                         const float* __restrict__ cb0,
                                                         const float* __restrict__ cw1,
                                                         const float* __restrict__ cb1,
                                                         float* __restrict__ out, int N) {
    int tid  = threadIdx.x;
    int warp = tid >> 5;
    int lane = tid & 31;
    int row  = blockIdx.x * 8 + warp;
    if (row >= N) return;

    float acc = spmm_row_v5(sup_in, row, lane);
    float h = selu_f(acc) + bias[lane];

    float p0 = h * cw0[lane];
    float p1 = h * cw0[32 + lane];
    float p2 = h * cw1[lane];
    float p3 = h * cw1[32 + lane];
    float p4 = h * cw1[64 + lane];
#pragma unroll
    for (int off = 16; off; off >>= 1) {
        p0 += __shfl_xor_sync(0xffffffffu, p0, off);
        p1 += __shfl_xor_sync(0xffffffffu, p1, off);
        p2 += __shfl_xor_sync(0xffffffffu, p2, off);
        p3 += __shfl_xor_sync(0xffffffffu, p3, off);
        p4 += __shfl_xor_sync(0xffffffffu, p4, off);
    }
    if (lane < 2) {
        out[(size_t)row * 2 + lane] = ((lane == 0) ? p0 : p1) + cb0[lane];
    } else if (lane < 5) {
        float pv = (lane == 2) ? p2 : ((lane == 3) ? p3 : p4);
        out[(size_t)N * 2 + (size_t)row * 3 + (lane - 2)] = pv + cb1[lane - 2];
    }
}

// ---------------------------------------------------------------------------
extern "C" void kernel_launch(void* const* d_in, const int* in_sizes, int n_in,
                              void* d_out, int out_size) {
    const float* x     = (const float*)d_in[0];
    const int*   arows = (const int*)d_in[1];
    const int*   acols = (const int*)d_in[2];
    const float* avals = (const float*)d_in[3];
    const float* w1    = (const float*)d_in[4];
    const float* b1    = (const float*)d_in[5];
    const float* w2    = (const float*)d_in[6];
    const float* b2    = (const float*)d_in[7];
    const float* w3    = (const float*)d_in[8];
    const float* b3    = (const float*)d_in[9];
    const float* cw0   = (const float*)d_in[10];
    const float* cb0   = (const float*)d_in[11];
    const float* cw1   = (const float*)d_in[12];
    const float* cb1   = (const float*)d_in[13];
    float* out = (float*)d_out;

    int N = in_sizes[0] / 1024;
    int E = in_sizes[1];

    float *bufA, *bufB;
    int* cnt;
    cudaGetSymbolAddress((void**)&bufA, g_bufA);
    cudaGetSymbolAddress((void**)&bufB, g_bufB);
    cudaGetSymbolAddress((void**)&cnt,  g_cnt);

    // one-time side-stream resources (host-side only; no device allocation)
    static cudaStream_t s1 = nullptr;
    static cudaEvent_t  eFork = nullptr, eJoin = nullptr;
    if (s1 == nullptr) {
        cudaStreamCreateWithFlags(&s1, cudaStreamNonBlocking);
        cudaEventCreateWithFlags(&eFork, cudaEventDisableTiming);
        cudaEventCreateWithFlags(&eJoin, cudaEventDisableTiming);
    }

    int gemmBlocks  = ((N + 127) / 128) * KSPLIT;
    int rowBlocks   = (N + 7) / 8;
    int edgeBlocks2 = (E / 2 + 255) / 256 + 1;

    // fork: CSR build path runs concurrently with gemm1
    cudaEventRecord(eFork, 0);
    cudaStreamWaitEvent(s1, eFork, 0);
    cudaMemsetAsync(cnt, 0, (size_t)N * sizeof(int), s1);
    build_csr_kernel<<<edgeBlocks2, 256, 0, s1>>>(arows, acols, avals, E);
    cudaEventRecord(eJoin, s1);

    // main stream: dense GEMM1 (independent of the CSR)
    cudaMemsetAsync(bufA, 0, (size_t)N * 32 * sizeof(float));
    gemm1_kernel<<<gemmBlocks, 128>>>(x, w1, bufA, N);

    // join: SpMM needs both gemm1 (main) and CSR (s1)
    cudaStreamWaitEvent(0, eJoin, 0);
    spmm_selu_gemm_kernel<<<rowBlocks, 256>>>(bufA, b1, w2, bufB, N);
    spmm_selu_gemm_kernel<<<rowBlocks, 256>>>(bufB, b2, w3, bufA, N);
    spmm_final_kernel<<<rowBlocks, 256>>>(bufA, b3, cw0, cb0, cw1, cb1, out, N);
}

// round 17
// speedup vs baseline: 1.4500x; 1.4500x over previous
#include <cuda_runtime.h>
#include <math.h>
#include <stdint.h>

#define NMAX 50000
#define CAP  128
#define KSPLIT 4

__device__ float g_bufA[NMAX * 32];
__device__ float g_bufB[NMAX * 32];
__device__ int2  g_csr[(size_t)NMAX * CAP];
__device__ int   g_cnt[NMAX];

__device__ __forceinline__ float selu_f(float x) {
    const float alpha = 1.6732632423543772f;
    const float scale = 1.0507009873554805f;
    return x > 0.f ? scale * x : scale * alpha * (expf(x) - 1.f);
}

typedef unsigned long long ull;
__device__ __forceinline__ ull pack2(float a) {
    ull r; asm("mov.b64 %0, {%1, %1};" : "=l"(r) : "f"(a)); return r;
}
__device__ __forceinline__ void fma2(ull& d, ull a, ull b) {
    asm("fma.rn.f32x2 %0, %1, %2, %3;" : "=l"(d) : "l"(a), "l"(b), "l"(d));
}

// ---------------------------------------------------------------------------
// CSR build: 2 edges per thread, vectorized meta loads (serial schedule).
// ---------------------------------------------------------------------------
__global__ void __launch_bounds__(256) build_csr_kernel(const int* __restrict__ rows,
                                                        const int* __restrict__ cols,
                                                        const float* __restrict__ vals,
                                                        int E) {
    int e = (blockIdx.x * 256 + threadIdx.x) * 2;
    if (e + 1 < E) {
        int2   rr = *(const int2*)(rows + e);
        int2   cc = *(const int2*)(cols + e);
        float2 vv = *(const float2*)(vals + e);
        int p0 = atomicAdd(&g_cnt[rr.x], 1);
        if (p0 < CAP)
            g_csr[(size_t)rr.x * CAP + p0] = make_int2(cc.x, __float_as_int(vv.x));
        int p1 = atomicAdd(&g_cnt[rr.y], 1);
        if (p1 < CAP)
            g_csr[(size_t)rr.y * CAP + p1] = make_int2(cc.y, __float_as_int(vv.y));
    } else if (e < E) {
        int r = rows[e];
        int p = atomicAdd(&g_cnt[r], 1);
        if (p < CAP)
            g_csr[(size_t)r * CAP + p] = make_int2(cols[e], __float_as_int(vals[e]));
    }
}

// ---------------------------------------------------------------------------
// GEMM1 (R13 measured-best, FROZEN): split-K x4, col-pair FFMA2 inner loop,
// RED.128 accumulate into zeroed sup.
// ---------------------------------------------------------------------------
__global__ void __launch_bounds__(128) gemm1_kernel(const float* __restrict__ x,
                                                    const float* __restrict__ w,
                                                    float* __restrict__ sup, int N) {
    __shared__ float xs[128][33];
    __shared__ float ws[32][32];

    int tid  = threadIdx.x;
    int rb   = blockIdx.x >> 2;
    int ks   = blockIdx.x & 3;
    int row0 = rb * 128;
    int kbeg = ks * 256;
    int trow = (tid >> 2) * 4;
    int tcol = (tid & 3) * 8;

    ull acc[4][4];
#pragma unroll
    for (int i = 0; i < 4; i++)
#pragma unroll
        for (int j = 0; j < 4; j++) acc[i][j] = 0ull;

    for (int kc = 0; kc < 8; kc++) {
        int k0 = kbeg + kc * 32;
#pragma unroll
        for (int i = 0; i < 2; i++) {
            int idx = i * 128 + tid;
            ((float4*)ws)[idx] = ((const float4*)(w + (size_t)k0 * 32))[idx];
        }
#pragma unroll
        for (int i = 0; i < 8; i++) {
            int idx = i * 128 + tid;
            int r   = idx >> 3;
            int kk  = (idx & 7) * 4;
            float4 v = make_float4(0.f, 0.f, 0.f, 0.f);
            if (row0 + r < N)
                v = *(const float4*)(x + (size_t)(row0 + r) * 1024 + k0 + kk);
            xs[r][kk] = v.x; xs[r][kk + 1] = v.y; xs[r][kk + 2] = v.z; xs[r][kk + 3] = v.w;
        }
        __syncthreads();

#pragma unroll
        for (int k = 0; k < 32; k++) {
            ull B[4];
#pragma unroll
            for (int j = 0; j < 4; j++) B[j] = *(const ull*)&ws[k][tcol + 2 * j];
#pragma unroll
            for (int i = 0; i < 4; i++) {
                ull A = pack2(xs[trow + i][k]);
                fma2(acc[i][0], A, B[0]);
                fma2(acc[i][1], A, B[1]);
                fma2(acc[i][2], A, B[2]);
                fma2(acc[i][3], A, B[3]);
            }
        }
        __syncthreads();
    }

#pragma unroll
    for (int i = 0; i < 4; i++) {
        int r = row0 + trow + i;
        if (r < N) {
            union { ull u; float2 f; } u0, u1, u2, u3;
            u0.u = acc[i][0]; u1.u = acc[i][1]; u2.u = acc[i][2]; u3.u = acc[i][3];
            float* dst = sup + (size_t)r * 32 + tcol;
            asm volatile("red.global.add.v4.f32 [%0], {%1,%2,%3,%4};"
                         :: "l"(dst), "f"(u0.f.x), "f"(u0.f.y), "f"(u1.f.x), "f"(u1.f.y)
                         : "memory");
            asm volatile("red.global.add.v4.f32 [%0], {%1,%2,%3,%4};"
                         :: "l"(dst + 4), "f"(u2.f.x), "f"(u2.f.y), "f"(u3.f.x), "f"(u3.f.y)
                         : "memory");
        }
    }
}

// ---------------------------------------------------------------------------
// SpMM core v5 (R12 measured-good): 4 lane-groups x float4.
// ---------------------------------------------------------------------------
__device__ __forceinline__ float spmm_row_v5(const float* __restrict__ sup,
                                             int row, int lane) {
    int deg = g_cnt[row];
    if (deg > CAP) deg = CAP;
    const int2* base = g_csr + (size_t)row * CAP;
    int g   = lane >> 3;
    int sub = lane & 7;

    float4 acc = make_float4(0.f, 0.f, 0.f, 0.f);

    for (int c0 = 0; c0 < deg; c0 += 32) {
        int rem = deg - c0;
        if (rem > 32) rem = 32;
        int2 ev = make_int2(0, 0);
        if (lane < rem) ev = base[c0 + lane];

        if (rem == 32) {
#pragma unroll
            for (int half = 0; half < 2; half++) {
                float4 sv[4]; float vv[4];
#pragma unroll
                for (int s = 0; s < 4; s++) {
                    int src = (half * 4 + s) * 4 + g;
                    int col = __shfl_sync(0xffffffffu, ev.x, src);
                    vv[s] = __int_as_float(__shfl_sync(0xffffffffu, ev.y, src));
                    sv[s] = __ldg((const float4*)(sup + (size_t)col * 32) + sub);
                }
#pragma unroll
                for (int s = 0; s < 4; s++) {
                    acc.x = fmaf(vv[s], sv[s].x, acc.x);
                    acc.y = fmaf(vv[s], sv[s].y, acc.y);
                    acc.z = fmaf(vv[s], sv[s].z, acc.z);
                    acc.w = fmaf(vv[s], sv[s].w, acc.w);
                }
            }
        } else {
            int nst = (rem + 3) >> 2;
            for (int s = 0; s < nst; s++) {
                int src = s * 4 + g;
                int col = __shfl_sync(0xffffffffu, ev.x, src);
                float v = __int_as_float(__shfl_sync(0xffffffffu, ev.y, src));
                float4 sv = __ldg((const float4*)(sup + (size_t)col * 32) + sub);
                acc.x = fmaf(v, sv.x, acc.x);
                acc.y = fmaf(v, sv.y, acc.y);
                acc.z = fmaf(v, sv.z, acc.z);
                acc.w = fmaf(v, sv.w, acc.w);
            }
        }
    }

#pragma unroll
    for (int off = 8; off <= 16; off <<= 1) {
        acc.x += __shfl_xor_sync(0xffffffffu, acc.x, off);
        acc.y += __shfl_xor_sync(0xffffffffu, acc.y, off);
        acc.z += __shfl_xor_sync(0xffffffffu, acc.z, off);
        acc.w += __shfl_xor_sync(0xffffffffu, acc.w, off);
    }

    int src = lane >> 2;
    float c0 = __shfl_sync(0xffffffffu, acc.x, src);
    float c1 = __shfl_sync(0xffffffffu, acc.y, src);
    float c2 = __shfl_sync(0xffffffffu, acc.z, src);
    float c3 = __shfl_sync(0xffffffffu, acc.w, src);
    int comp = lane & 3;
    return comp == 0 ? c0 : comp == 1 ? c1 : comp == 2 ? c2 : c3;
}

// ---------------------------------------------------------------------------
// Fused: agg = SpMM(sup_in); h = selu(agg)+b; sup_out = h @ w
// __launch_bounds__(256, 8): cap at 32 regs -> 8 blocks/SM (was 40 regs/6).
// ---------------------------------------------------------------------------
__global__ void __launch_bounds__(256, 8) spmm_selu_gemm_kernel(const float* __restrict__ sup_in,
                                                                const float* __restrict__ bias,
                                                                const float* __restrict__ w,
                                                                float* __restrict__ sup_out,
                                                                int N) {
    __shared__ float ws[1024];
    __shared__ float bs[32];
    int tid = threadIdx.x;
    for (int i = tid; i < 1024; i += 256) ws[i] = w[i];
    if (tid < 32) bs[tid] = bias[tid];
    __syncthreads();

    int warp = tid >> 5;
    int lane = tid & 31;
    int row  = blockIdx.x * 8 + warp;
    if (row >= N) return;

    float acc = spmm_row_v5(sup_in, row, lane);
    float h = selu_f(acc) + bs[lane];

    float o = 0.f;
#pragma unroll
    for (int k = 0; k < 32; k++) {
        float hk = __shfl_sync(0xffffffffu, h, k);
        o = fmaf(hk, ws[k * 32 + lane], o);
    }
    sup_out[(size_t)row * 32 + lane] = o;
}

// ---------------------------------------------------------------------------
// Fused final: agg = SpMM; h = selu+b3; classifier heads → out
// ---------------------------------------------------------------------------
__global__ void __launch_bounds__(256, 8) spmm_final_kernel(const float* __restrict__ sup_in,
                                                            const float* __restrict__ bias,
                                                            const float* __restrict__ cw0,
                                                            const float* __restrict__ cb0,
                                                            const float* __restrict__ cw1,
                                                            const float* __restrict__ cb1,
                                                            float* __restrict__ out, int N) {
    int tid  = threadIdx.x;
    int warp = tid >> 5;
    int lane = tid & 31;
    int row  = blockIdx.x * 8 + warp;
    if (row >= N) return;

    float acc = spmm_row_v5(sup_in, row, lane);
    float h = selu_f(acc) + bias[lane];

    float p0 = h * cw0[lane];
    float p1 = h * cw0[32 + lane];
    float p2 = h * cw1[lane];
    float p3 = h * cw1[32 + lane];
    float p4 = h * cw1[64 + lane];
#pragma unroll
    for (int off = 16; off; off >>= 1) {
        p0 += __shfl_xor_sync(0xffffffffu, p0, off);
        p1 += __shfl_xor_sync(0xffffffffu, p1, off);
        p2 += __shfl_xor_sync(0xffffffffu, p2, off);
        p3 += __shfl_xor_sync(0xffffffffu, p3, off);
        p4 += __shfl_xor_sync(0xffffffffu, p4, off);
    }
    if (lane < 2) {
        out[(size_t)row * 2 + lane] = ((lane == 0) ? p0 : p1) + cb0[lane];
    } else if (lane < 5) {
        float pv = (lane == 2) ? p2 : ((lane == 3) ? p3 : p4);
        out[(size_t)N * 2 + (size_t)row * 3 + (lane - 2)] = pv + cb1[lane - 2];
    }
}

// ---------------------------------------------------------------------------
extern "C" void kernel_launch(void* const* d_in, const int* in_sizes, int n_in,
                              void* d_out, int out_size) {
    const float* x     = (const float*)d_in[0];
    const int*   arows = (const int*)d_in[1];
    const int*   acols = (const int*)d_in[2];
    const float* avals = (const float*)d_in[3];
    const float* w1    = (const float*)d_in[4];
    const float* b1    = (const float*)d_in[5];
    const float* w2    = (const float*)d_in[6];
    const float* b2    = (const float*)d_in[7];
    const float* w3    = (const float*)d_in[8];
    const float* b3    = (const float*)d_in[9];
    const float* cw0   = (const float*)d_in[10];
    const float* cb0   = (const float*)d_in[11];
    const float* cw1   = (const float*)d_in[12];
    const float* cb1   = (const float*)d_in[13];
    float* out = (float*)d_out;

    int N = in_sizes[0] / 1024;
    int E = in_sizes[1];

    float *bufA, *bufB;
    int* cnt;
    cudaGetSymbolAddress((void**)&bufA, g_bufA);
    cudaGetSymbolAddress((void**)&bufB, g_bufB);
    cudaGetSymbolAddress((void**)&cnt,  g_cnt);

    int gemmBlocks  = ((N + 127) / 128) * KSPLIT;
    int rowBlocks   = (N + 7) / 8;
    int edgeBlocks2 = (E / 2 + 255) / 256 + 1;

    cudaMemsetAsync(cnt, 0, (size_t)N * sizeof(int));
    cudaMemsetAsync(bufA, 0, (size_t)N * 32 * sizeof(float));
    build_csr_kernel<<<edgeBlocks2, 256>>>(arows, acols, avals, E);

    gemm1_kernel<<<gemmBlocks, 128>>>(x, w1, bufA, N);
    spmm_selu_gemm_kernel<<<rowBlocks, 256>>>(bufA, b1, w2, bufB, N);
    spmm_selu_gemm_kernel<<<rowBlocks, 256>>>(bufB, b2, w3, bufA, N);
    spmm_final_kernel<<<rowBlocks, 256>>>(bufA, b3, cw0, cb0, cw1, cb1, out, N);
}